// round 2
// baseline (speedup 1.0000x reference)
#include <cuda_runtime.h>
#include <math.h>

#define NSRC 50000
#define NDST 50000
#define EMAX 1600000

// ---------------- scratch (static device globals; no allocs) ----------------
__device__ float g_hs[(size_t)NSRC * 128];     // h_src @ W_src
__device__ float g_esrc[NSRC * 4];             // per-src-node logit component
__device__ float g_edst[NDST * 4];             // per-dst-node logit component
__device__ float g_elog[(size_t)EMAX * 4];     // per-edge leaky logits (orig order)
__device__ float g_selog[(size_t)EMAX * 4];    // dst-sorted logits
__device__ int   g_ssrc[EMAX];                 // dst-sorted src indices
__device__ int   g_count[NDST + 1];
__device__ int   g_off[NDST + 1];
__device__ int   g_cur[NDST];
__device__ float g_csrc[128 * 4];              // c[k][h] layouts (float4 per k)
__device__ float g_cdst[128 * 4];
__device__ float g_cedge[64 * 4];

// ---------------- K0: fold W,a -> c vectors; zero histogram ----------------
__global__ void k0_prep(const float* __restrict__ Wsrc, const float* __restrict__ Wdst,
                        const float* __restrict__ Wedge, const float* __restrict__ asrc,
                        const float* __restrict__ adst, const float* __restrict__ aedge,
                        int ndst) {
    int t = blockIdx.x * blockDim.x + threadIdx.x;
    int stride = gridDim.x * blockDim.x;
    for (int i = t; i <= ndst; i += stride) g_count[i] = 0;
    if (blockIdx.x == 0) {
        for (int i = threadIdx.x; i < 128 * 4; i += blockDim.x) {
            int k = i >> 2, h = i & 3;
            float s1 = 0.f, s2 = 0.f;
            #pragma unroll
            for (int d = 0; d < 32; d++) {
                s1 += Wsrc[k * 128 + h * 32 + d] * asrc[h * 32 + d];
                s2 += Wdst[k * 128 + h * 32 + d] * adst[h * 32 + d];
            }
            g_csrc[i] = s1;
            g_cdst[i] = s2;
        }
        for (int i = threadIdx.x; i < 64 * 4; i += blockDim.x) {
            int k = i >> 2, h = i & 3;
            float s = 0.f;
            #pragma unroll
            for (int d = 0; d < 32; d++)
                s += Wedge[k * 128 + h * 32 + d] * aedge[h * 32 + d];
            g_cedge[i] = s;
        }
    }
}

// ---------------- K1: hs = h_src @ W_src  (smem-tiled fp32 GEMM) ----------------
// Block: 256 threads computing a 64-row x 128-col output tile.
// Thread tile: 8 rows x 4 cols (float4). K split into two 64-chunks.
__global__ void k1_gemm(const float* __restrict__ x, const float* __restrict__ W, int nrows) {
    extern __shared__ float smem[];
    float* Ws = smem;            // [64][128]  = 32KB
    float* Xs = smem + 64 * 128; // [64][64]   = 16KB
    const int tid = threadIdx.x;
    const int row0 = blockIdx.x * 64;
    const int c0 = (tid & 31) * 4;
    const int rbase = (tid >> 5) * 8;

    float4 acc[8];
    #pragma unroll
    for (int r = 0; r < 8; r++) acc[r] = make_float4(0.f, 0.f, 0.f, 0.f);

    for (int kb = 0; kb < 128; kb += 64) {
        for (int i = tid; i < 64 * 128; i += 256) {
            int k = i >> 7, c = i & 127;
            Ws[i] = W[(kb + k) * 128 + c];
        }
        for (int i = tid; i < 64 * 64; i += 256) {
            int r = i >> 6, kk = i & 63;
            int gr = row0 + r;
            Xs[i] = (gr < nrows) ? x[(size_t)gr * 128 + kb + kk] : 0.f;
        }
        __syncthreads();
        #pragma unroll 4
        for (int k = 0; k < 64; k++) {
            float4 w4 = *reinterpret_cast<const float4*>(&Ws[k * 128 + c0]);
            #pragma unroll
            for (int rr = 0; rr < 8; rr++) {
                float xv = Xs[(rbase + rr) * 64 + k];
                acc[rr].x += xv * w4.x;
                acc[rr].y += xv * w4.y;
                acc[rr].z += xv * w4.z;
                acc[rr].w += xv * w4.w;
            }
        }
        __syncthreads();
    }
    #pragma unroll
    for (int rr = 0; rr < 8; rr++) {
        int gr = row0 + rbase + rr;
        if (gr < nrows)
            *reinterpret_cast<float4*>(&g_hs[(size_t)gr * 128 + c0]) = acc[rr];
    }
}

// ---------------- K2: per-node logit components (warp per row) ----------------
__global__ void k2_node(const float* __restrict__ hsrc, const float* __restrict__ hdst,
                        int nsrc, int ndst) {
    int warp = (blockIdx.x * blockDim.x + threadIdx.x) >> 5;
    int lane = threadIdx.x & 31;
    if (warp >= nsrc + ndst) return;
    const float* x;
    const float* c;
    float* outp;
    if (warp < nsrc) { x = hsrc + (size_t)warp * 128; c = g_csrc; outp = g_esrc + warp * 4; }
    else { int n = warp - nsrc; x = hdst + (size_t)n * 128; c = g_cdst; outp = g_edst + n * 4; }

    float4 xv = reinterpret_cast<const float4*>(x)[lane];
    const float4* c4 = reinterpret_cast<const float4*>(c);
    int k = lane * 4;
    float4 a = make_float4(0.f, 0.f, 0.f, 0.f);
    float4 c0v = c4[k], c1v = c4[k + 1], c2v = c4[k + 2], c3v = c4[k + 3];
    a.x = xv.x * c0v.x + xv.y * c1v.x + xv.z * c2v.x + xv.w * c3v.x;
    a.y = xv.x * c0v.y + xv.y * c1v.y + xv.z * c2v.y + xv.w * c3v.y;
    a.z = xv.x * c0v.z + xv.y * c1v.z + xv.z * c2v.z + xv.w * c3v.z;
    a.w = xv.x * c0v.w + xv.y * c1v.w + xv.z * c2v.w + xv.w * c3v.w;
    #pragma unroll
    for (int off = 16; off; off >>= 1) {
        a.x += __shfl_xor_sync(0xffffffffu, a.x, off);
        a.y += __shfl_xor_sync(0xffffffffu, a.y, off);
        a.z += __shfl_xor_sync(0xffffffffu, a.z, off);
        a.w += __shfl_xor_sync(0xffffffffu, a.w, off);
    }
    if (lane == 0) *reinterpret_cast<float4*>(outp) = a;
}

// ---------------- K3: edge logits + leaky relu + dst histogram ----------------
#define EPB 128
__global__ void k3_edge(const float* __restrict__ efeat, const int* __restrict__ ei, int E) {
    __shared__ float sx[EPB * 65];
    __shared__ float4 sc[64];
    const int tid = threadIdx.x;
    const int base = blockIdx.x * EPB;
    if (tid < 64) sc[tid] = reinterpret_cast<const float4*>(g_cedge)[tid];
    int cnt = E - base;
    if (cnt > EPB) cnt = EPB;
    for (int i = tid; i < cnt * 64; i += EPB) {
        int r = i >> 6, col = i & 63;
        sx[r * 65 + col] = efeat[(size_t)base * 64 + i];
    }
    __syncthreads();
    if (tid < cnt) {
        int e = base + tid;
        const float* row = &sx[tid * 65];
        float4 s = make_float4(0.f, 0.f, 0.f, 0.f);
        #pragma unroll
        for (int k = 0; k < 64; k++) {
            float xv = row[k];
            float4 c = sc[k];
            s.x += xv * c.x; s.y += xv * c.y; s.z += xv * c.z; s.w += xv * c.w;
        }
        int src = ei[e];
        int dst = ei[E + e];
        float4 es = reinterpret_cast<const float4*>(g_esrc)[src];
        float4 ed = reinterpret_cast<const float4*>(g_edst)[dst];
        s.x += es.x + ed.x; s.y += es.y + ed.y; s.z += es.z + ed.z; s.w += es.w + ed.w;
        s.x = s.x > 0.f ? s.x : 0.2f * s.x;
        s.y = s.y > 0.f ? s.y : 0.2f * s.y;
        s.z = s.z > 0.f ? s.z : 0.2f * s.z;
        s.w = s.w > 0.f ? s.w : 0.2f * s.w;
        reinterpret_cast<float4*>(g_elog)[e] = s;
        atomicAdd(&g_count[dst], 1);
    }
}

// ---------------- K4: exclusive scan of histogram (single block) ----------------
__global__ void k4_scan(int n) {
    __shared__ int ssum[1024];
    const int t = threadIdx.x;
    const int chunk = (n + 1023) >> 10;
    const int b = t * chunk;
    int e = b + chunk;
    if (e > n) e = n;
    int s = 0;
    for (int i = b; i < e; i++) s += g_count[i];
    ssum[t] = s;
    __syncthreads();
    for (int off = 1; off < 1024; off <<= 1) {
        int v = (t >= off) ? ssum[t - off] : 0;
        __syncthreads();
        ssum[t] += v;
        __syncthreads();
    }
    int run = (t == 0) ? 0 : ssum[t - 1];
    for (int i = b; i < e; i++) {
        g_off[i] = run;
        g_cur[i] = run;
        run += g_count[i];
    }
    if (t == 1023) g_off[n] = ssum[1023];
}

// ---------------- K5: scatter edges into dst-sorted order ----------------
__global__ void k5_scatter(const int* __restrict__ ei, int E) {
    int e = blockIdx.x * blockDim.x + threadIdx.x;
    if (e >= E) return;
    int dst = ei[E + e];
    int pos = atomicAdd(&g_cur[dst], 1);
    g_ssrc[pos] = ei[e];
    reinterpret_cast<float4*>(g_selog)[pos] = reinterpret_cast<const float4*>(g_elog)[e];
}

// ---------------- K6: per-dst softmax + weighted gather-aggregate ----------------
__device__ __forceinline__ void online_upd(float& m, float& s, float v) {
    float nm = fmaxf(m, v);
    s = s * __expf(m - nm) + __expf(v - nm);
    m = nm;
}
__device__ __forceinline__ void warp_merge(float& m, float& s) {
    #pragma unroll
    for (int off = 16; off; off >>= 1) {
        float om = __shfl_xor_sync(0xffffffffu, m, off);
        float os = __shfl_xor_sync(0xffffffffu, s, off);
        float M = fmaxf(m, om);
        s = s * __expf(m - M) + os * __expf(om - M);
        m = M;
    }
}

__global__ void k6_agg(float* __restrict__ out, int ndst) {
    int warp = (blockIdx.x * blockDim.x + threadIdx.x) >> 5;
    int lane = threadIdx.x & 31;
    if (warp >= ndst) return;
    int beg = g_off[warp];
    int end = g_off[warp + 1];
    float4* orow = reinterpret_cast<float4*>(out + (size_t)warp * 128);
    if (beg == end) {
        orow[lane] = make_float4(0.f, 0.f, 0.f, 0.f);
        return;
    }
    float m0 = -1e30f, m1 = -1e30f, m2 = -1e30f, m3 = -1e30f;
    float s0 = 0.f, s1 = 0.f, s2 = 0.f, s3 = 0.f;
    for (int i = beg + lane; i < end; i += 32) {
        float4 ev = reinterpret_cast<const float4*>(g_selog)[i];
        online_upd(m0, s0, ev.x);
        online_upd(m1, s1, ev.y);
        online_upd(m2, s2, ev.z);
        online_upd(m3, s3, ev.w);
    }
    warp_merge(m0, s0);
    warp_merge(m1, s1);
    warp_merge(m2, s2);
    warp_merge(m3, s3);
    const int myh = lane >> 3;
    float mh = (myh == 0) ? m0 : (myh == 1) ? m1 : (myh == 2) ? m2 : m3;
    float sh = (myh == 0) ? s0 : (myh == 1) ? s1 : (myh == 2) ? s2 : s3;
    float invh = 1.f / (sh + 1e-8f);

    float4 acc = make_float4(0.f, 0.f, 0.f, 0.f);
    for (int i = beg; i < end; i++) {
        float4 ev = reinterpret_cast<const float4*>(g_selog)[i];
        float e = (myh == 0) ? ev.x : (myh == 1) ? ev.y : (myh == 2) ? ev.z : ev.w;
        float alpha = __expf(e - mh) * invh;
        int src = g_ssrc[i];
        float4 xv = reinterpret_cast<const float4*>(g_hs + (size_t)src * 128)[lane];
        acc.x += alpha * xv.x;
        acc.y += alpha * xv.y;
        acc.z += alpha * xv.z;
        acc.w += alpha * xv.w;
    }
    orow[lane] = acc;
}

// ---------------- launch ----------------
extern "C" void kernel_launch(void* const* d_in, const int* in_sizes, int n_in,
                              void* d_out, int out_size) {
    const float* h_src   = (const float*)d_in[0];
    const float* h_dst   = (const float*)d_in[1];
    const float* e_feat  = (const float*)d_in[2];
    const int*   ei      = (const int*)d_in[3];
    const float* W_src   = (const float*)d_in[4];
    const float* W_dst   = (const float*)d_in[5];
    const float* W_edge  = (const float*)d_in[6];
    const float* a_src   = (const float*)d_in[7];
    const float* a_dst   = (const float*)d_in[8];
    const float* a_edge  = (const float*)d_in[9];
    float* out = (float*)d_out;

    const int nsrc = in_sizes[0] / 128;
    const int ndst = in_sizes[1] / 128;
    const int E    = in_sizes[3] / 2;

    k0_prep<<<200, 256>>>(W_src, W_dst, W_edge, a_src, a_dst, a_edge, ndst);

    const int smem1 = (64 * 128 + 64 * 64) * (int)sizeof(float);  // 48KB
    cudaFuncSetAttribute(k1_gemm, cudaFuncAttributeMaxDynamicSharedMemorySize, smem1);
    k1_gemm<<<(nsrc + 63) / 64, 256, smem1>>>(h_src, W_src, nsrc);

    int warps = nsrc + ndst;
    k2_node<<<(warps + 7) / 8, 256>>>(h_src, h_dst, nsrc, ndst);

    k3_edge<<<(E + EPB - 1) / EPB, EPB>>>(e_feat, ei, E);

    k4_scan<<<1, 1024>>>(ndst);

    k5_scatter<<<(E + 255) / 256, 256>>>(ei, E);

    k6_agg<<<(ndst + 7) / 8, 256>>>(out, ndst);

    (void)n_in; (void)out_size;
}

// round 6
// speedup vs baseline: 1.4322x; 1.4322x over previous
#include <cuda_runtime.h>
#include <math.h>

#define NSRC 50000
#define NDST 50000
#define EMAX 1600000

// ---------------- scratch (static device globals; no allocs) ----------------
__device__ float g_hs[(size_t)NSRC * 128];     // h_src @ W_src
__device__ float g_esrc[NSRC * 4];             // per-src-node logit component
__device__ float g_edst[NDST * 4];             // per-dst-node logit component
__device__ float g_elog[(size_t)EMAX * 4];     // per-edge leaky logits (orig order)
__device__ float g_selog[(size_t)EMAX * 4];    // dst-sorted logits
__device__ int   g_ssrc[EMAX];                 // dst-sorted src indices
__device__ int   g_count[NDST + 1];
__device__ int   g_off[NDST + 1];
__device__ int   g_cur[NDST];
__device__ float g_cdst[128 * 4];              // folded W_dst·a_dst, c[k][h]
__device__ float g_cedge[64 * 4];              // folded W_edge·a_edge

// ---------------- K0: fold W,a -> c vectors; zero histogram ----------------
__global__ void k0_prep(const float* __restrict__ Wdst, const float* __restrict__ Wedge,
                        const float* __restrict__ adst, const float* __restrict__ aedge,
                        int ndst) {
    int t = blockIdx.x * blockDim.x + threadIdx.x;
    int stride = gridDim.x * blockDim.x;
    for (int i = t; i <= ndst; i += stride) g_count[i] = 0;
    if (blockIdx.x == 0) {
        for (int i = threadIdx.x; i < 128 * 4; i += blockDim.x) {
            int k = i >> 2, h = i & 3;
            float s2 = 0.f;
            #pragma unroll
            for (int d = 0; d < 32; d++)
                s2 += Wdst[k * 128 + h * 32 + d] * adst[h * 32 + d];
            g_cdst[i] = s2;
        }
        for (int i = threadIdx.x; i < 64 * 4; i += blockDim.x) {
            int k = i >> 2, h = i & 3;
            float s = 0.f;
            #pragma unroll
            for (int d = 0; d < 32; d++)
                s += Wedge[k * 128 + h * 32 + d] * aedge[h * 32 + d];
            g_cedge[i] = s;
        }
    }
}

// ---------------- K1: hs = h_src @ W_src + fused e_src epilogue ----------------
// Block: 256 threads, 64-row x 128-col output tile. Thread: 8 rows x 4 cols.
// e_src[n][h] = sum_d hs[n][h*32+d] * a_src[h][d]  -> dot acc with FLAT a_src.
__global__ void k1_gemm(const float* __restrict__ x, const float* __restrict__ W,
                        const float* __restrict__ asrc, int nrows) {
    extern __shared__ float smem[];
    float* Ws = smem;            // [64][128]  = 32KB
    float* Xs = smem + 64 * 128; // [64][64]   = 16KB
    const int tid = threadIdx.x;
    const int row0 = blockIdx.x * 64;
    const int lane = tid & 31;
    const int c0 = lane * 4;
    const int rbase = (tid >> 5) * 8;

    float4 acc[8];
    #pragma unroll
    for (int r = 0; r < 8; r++) acc[r] = make_float4(0.f, 0.f, 0.f, 0.f);

    for (int kb = 0; kb < 128; kb += 64) {
        for (int i = tid; i < 64 * 128; i += 256) {
            int k = i >> 7, c = i & 127;
            Ws[i] = W[(kb + k) * 128 + c];
        }
        for (int i = tid; i < 64 * 64; i += 256) {
            int r = i >> 6, kk = i & 63;
            int gr = row0 + r;
            Xs[i] = (gr < nrows) ? x[(size_t)gr * 128 + kb + kk] : 0.f;
        }
        __syncthreads();
        #pragma unroll 4
        for (int k = 0; k < 64; k++) {
            float4 w4 = *reinterpret_cast<const float4*>(&Ws[k * 128 + c0]);
            #pragma unroll
            for (int rr = 0; rr < 8; rr++) {
                float xv = Xs[(rbase + rr) * 64 + k];
                acc[rr].x += xv * w4.x;
                acc[rr].y += xv * w4.y;
                acc[rr].z += xv * w4.z;
                acc[rr].w += xv * w4.w;
            }
        }
        __syncthreads();
    }
    // store hs
    #pragma unroll
    for (int rr = 0; rr < 8; rr++) {
        int gr = row0 + rbase + rr;
        if (gr < nrows)
            *reinterpret_cast<float4*>(&g_hs[(size_t)gr * 128 + c0]) = acc[rr];
    }
    // fused e_src: dot output columns with flat a_src ([H,D] contiguous = [128])
    const int h = lane >> 3;               // head owned by this lane's 4 columns
    const float4 a4 = *reinterpret_cast<const float4*>(&asrc[c0]);
    #pragma unroll
    for (int rr = 0; rr < 8; rr++) {
        float p = acc[rr].x * a4.x + acc[rr].y * a4.y + acc[rr].z * a4.z + acc[rr].w * a4.w;
        p += __shfl_xor_sync(0xffffffffu, p, 1);
        p += __shfl_xor_sync(0xffffffffu, p, 2);
        p += __shfl_xor_sync(0xffffffffu, p, 4);
        int gr = row0 + rbase + rr;
        if ((lane & 7) == 0 && gr < nrows)
            g_esrc[gr * 4 + h] = p;
    }
}

// ---------------- K2: dst-node logit components (warp per row) ----------------
__global__ void k2_node(const float* __restrict__ hdst, int ndst) {
    int warp = (blockIdx.x * blockDim.x + threadIdx.x) >> 5;
    int lane = threadIdx.x & 31;
    if (warp >= ndst) return;
    const float* x = hdst + (size_t)warp * 128;
    float4 xv = reinterpret_cast<const float4*>(x)[lane];
    const float4* c4 = reinterpret_cast<const float4*>(g_cdst);
    int k = lane * 4;
    float4 c0v = c4[k], c1v = c4[k + 1], c2v = c4[k + 2], c3v = c4[k + 3];
    float4 a;
    a.x = xv.x * c0v.x + xv.y * c1v.x + xv.z * c2v.x + xv.w * c3v.x;
    a.y = xv.x * c0v.y + xv.y * c1v.y + xv.z * c2v.y + xv.w * c3v.y;
    a.z = xv.x * c0v.z + xv.y * c1v.z + xv.z * c2v.z + xv.w * c3v.z;
    a.w = xv.x * c0v.w + xv.y * c1v.w + xv.z * c2v.w + xv.w * c3v.w;
    #pragma unroll
    for (int off = 16; off; off >>= 1) {
        a.x += __shfl_xor_sync(0xffffffffu, a.x, off);
        a.y += __shfl_xor_sync(0xffffffffu, a.y, off);
        a.z += __shfl_xor_sync(0xffffffffu, a.z, off);
        a.w += __shfl_xor_sync(0xffffffffu, a.w, off);
    }
    if (lane == 0) reinterpret_cast<float4*>(g_edst)[warp] = a;
}

// ---------------- K3: edge logits + leaky relu + dst histogram ----------------
// 8 lanes per edge, no staging smem. Perfectly coalesced 512B warp loads.
__global__ void k3_edge(const float* __restrict__ efeat, const int* __restrict__ ei, int E) {
    __shared__ float4 sc[64];
    const int tid = threadIdx.x;
    if (tid < 64) sc[tid] = reinterpret_cast<const float4*>(g_cedge)[tid];
    __syncthreads();
    const int lane = tid & 31;
    const int g = lane >> 3;            // edge slot within warp (0..3)
    const int sub = lane & 7;           // 8 lanes per edge
    const int gwarp = (blockIdx.x * blockDim.x + tid) >> 5;
    const int e = gwarp * 4 + g;
    float4 s = make_float4(0.f, 0.f, 0.f, 0.f);
    if (e < E) {
        const float4* x4 = reinterpret_cast<const float4*>(efeat + (size_t)e * 64);
        float4 x0 = x4[sub];
        float4 x1 = x4[8 + sub];
        int k0 = sub * 4;
        s.x += x0.x * sc[k0 + 0].x + x0.y * sc[k0 + 1].x + x0.z * sc[k0 + 2].x + x0.w * sc[k0 + 3].x;
        s.y += x0.x * sc[k0 + 0].y + x0.y * sc[k0 + 1].y + x0.z * sc[k0 + 2].y + x0.w * sc[k0 + 3].y;
        s.z += x0.x * sc[k0 + 0].z + x0.y * sc[k0 + 1].z + x0.z * sc[k0 + 2].z + x0.w * sc[k0 + 3].z;
        s.w += x0.x * sc[k0 + 0].w + x0.y * sc[k0 + 1].w + x0.z * sc[k0 + 2].w + x0.w * sc[k0 + 3].w;
        int k1i = 32 + sub * 4;
        s.x += x1.x * sc[k1i + 0].x + x1.y * sc[k1i + 1].x + x1.z * sc[k1i + 2].x + x1.w * sc[k1i + 3].x;
        s.y += x1.x * sc[k1i + 0].y + x1.y * sc[k1i + 1].y + x1.z * sc[k1i + 2].y + x1.w * sc[k1i + 3].y;
        s.z += x1.x * sc[k1i + 0].z + x1.y * sc[k1i + 1].z + x1.z * sc[k1i + 2].z + x1.w * sc[k1i + 3].z;
        s.w += x1.x * sc[k1i + 0].w + x1.y * sc[k1i + 1].w + x1.z * sc[k1i + 2].w + x1.w * sc[k1i + 3].w;
    }
    #pragma unroll
    for (int off = 1; off < 8; off <<= 1) {
        s.x += __shfl_xor_sync(0xffffffffu, s.x, off);
        s.y += __shfl_xor_sync(0xffffffffu, s.y, off);
        s.z += __shfl_xor_sync(0xffffffffu, s.z, off);
        s.w += __shfl_xor_sync(0xffffffffu, s.w, off);
    }
    if (sub == 0 && e < E) {
        int src = ei[e];
        int dst = ei[E + e];
        float4 es = reinterpret_cast<const float4*>(g_esrc)[src];
        float4 ed = reinterpret_cast<const float4*>(g_edst)[dst];
        s.x += es.x + ed.x; s.y += es.y + ed.y; s.z += es.z + ed.z; s.w += es.w + ed.w;
        s.x = s.x > 0.f ? s.x : 0.2f * s.x;
        s.y = s.y > 0.f ? s.y : 0.2f * s.y;
        s.z = s.z > 0.f ? s.z : 0.2f * s.z;
        s.w = s.w > 0.f ? s.w : 0.2f * s.w;
        reinterpret_cast<float4*>(g_elog)[e] = s;
        atomicAdd(&g_count[dst], 1);
    }
}

// ---------------- K4: exclusive scan of histogram (single block) ----------------
__global__ void k4_scan(int n) {
    __shared__ int ssum[1024];
    const int t = threadIdx.x;
    const int chunk = (n + 1023) >> 10;
    const int b = t * chunk;
    int e = b + chunk;
    if (e > n) e = n;
    int s = 0;
    for (int i = b; i < e; i++) s += g_count[i];
    ssum[t] = s;
    __syncthreads();
    for (int off = 1; off < 1024; off <<= 1) {
        int v = (t >= off) ? ssum[t - off] : 0;
        __syncthreads();
        ssum[t] += v;
        __syncthreads();
    }
    int run = (t == 0) ? 0 : ssum[t - 1];
    for (int i = b; i < e; i++) {
        g_off[i] = run;
        g_cur[i] = run;
        run += g_count[i];
    }
    if (t == 1023) g_off[n] = ssum[1023];
}

// ---------------- K5: scatter edges into dst-sorted order ----------------
__global__ void k5_scatter(const int* __restrict__ ei, int E) {
    int e = blockIdx.x * blockDim.x + threadIdx.x;
    if (e >= E) return;
    int src = ei[e];
    int dst = ei[E + e];
    float4 ev = reinterpret_cast<const float4*>(g_elog)[e];
    int pos = atomicAdd(&g_cur[dst], 1);
    g_ssrc[pos] = src;
    reinterpret_cast<float4*>(g_selog)[pos] = ev;
}

// ---------------- K6: per-dst softmax + weighted gather-aggregate ----------------
__device__ __forceinline__ void online_upd(float& m, float& s, float v) {
    float nm = fmaxf(m, v);
    s = s * __expf(m - nm) + __expf(v - nm);
    m = nm;
}
__device__ __forceinline__ void warp_merge(float& m, float& s) {
    #pragma unroll
    for (int off = 16; off; off >>= 1) {
        float om = __shfl_xor_sync(0xffffffffu, m, off);
        float os = __shfl_xor_sync(0xffffffffu, s, off);
        float M = fmaxf(m, om);
        s = s * __expf(m - M) + os * __expf(om - M);
        m = M;
    }
}

__global__ void k6_agg(float* __restrict__ out, int ndst) {
    __shared__ float s_alpha[8][32 * 4];   // per-warp: 32 edges x 4 heads
    __shared__ int   s_idx[8][32];
    const int wslot = threadIdx.x >> 5;
    const int warp = (blockIdx.x * blockDim.x + threadIdx.x) >> 5;
    const int lane = threadIdx.x & 31;
    if (warp >= ndst) return;
    const int beg = g_off[warp];
    const int end = g_off[warp + 1];
    float4* orow = reinterpret_cast<float4*>(out + (size_t)warp * 128);
    if (beg == end) {
        orow[lane] = make_float4(0.f, 0.f, 0.f, 0.f);
        return;
    }
    const float4* selog4 = reinterpret_cast<const float4*>(g_selog);
    // pass 1: softmax stats
    float m0 = -1e30f, m1 = -1e30f, m2 = -1e30f, m3 = -1e30f;
    float s0 = 0.f, s1 = 0.f, s2 = 0.f, s3 = 0.f;
    for (int i = beg + lane; i < end; i += 32) {
        float4 ev = selog4[i];
        online_upd(m0, s0, ev.x);
        online_upd(m1, s1, ev.y);
        online_upd(m2, s2, ev.z);
        online_upd(m3, s3, ev.w);
    }
    warp_merge(m0, s0);
    warp_merge(m1, s1);
    warp_merge(m2, s2);
    warp_merge(m3, s3);
    const float i0 = 1.f / (s0 + 1e-8f);
    const float i1 = 1.f / (s1 + 1e-8f);
    const float i2 = 1.f / (s2 + 1e-8f);
    const float i3 = 1.f / (s3 + 1e-8f);
    const int myh = lane >> 3;

    const float4* hs4 = reinterpret_cast<const float4*>(g_hs);
    float4 acc = make_float4(0.f, 0.f, 0.f, 0.f);
    for (int base = beg; base < end; base += 32) {
        int myi = base + lane;
        if (myi < end) {
            float4 ev = selog4[myi];
            float4 af;
            af.x = __expf(ev.x - m0) * i0;
            af.y = __expf(ev.y - m1) * i1;
            af.z = __expf(ev.z - m2) * i2;
            af.w = __expf(ev.w - m3) * i3;
            reinterpret_cast<float4*>(&s_alpha[wslot][0])[lane] = af;
            s_idx[wslot][lane] = g_ssrc[myi];
        }
        __syncwarp();
        int n = end - base;
        if (n > 32) n = 32;
        const float* ap = &s_alpha[wslot][myh];
        #pragma unroll 4
        for (int j = 0; j < n; j++) {
            float al = ap[j * 4];                 // alpha of edge j for my head
            int src = s_idx[wslot][j];
            float4 xv = hs4[(size_t)src * 32 + lane];
            acc.x += al * xv.x;
            acc.y += al * xv.y;
            acc.z += al * xv.z;
            acc.w += al * xv.w;
        }
        __syncwarp();
    }
    orow[lane] = acc;
}

// ---------------- launch ----------------
extern "C" void kernel_launch(void* const* d_in, const int* in_sizes, int n_in,
                              void* d_out, int out_size) {
    const float* h_src   = (const float*)d_in[0];
    const float* h_dst   = (const float*)d_in[1];
    const float* e_feat  = (const float*)d_in[2];
    const int*   ei      = (const int*)d_in[3];
    const float* W_src   = (const float*)d_in[4];
    const float* W_dst   = (const float*)d_in[5];
    const float* W_edge  = (const float*)d_in[6];
    const float* a_src   = (const float*)d_in[7];
    const float* a_dst   = (const float*)d_in[8];
    const float* a_edge  = (const float*)d_in[9];
    float* out = (float*)d_out;

    const int nsrc = in_sizes[0] / 128;
    const int ndst = in_sizes[1] / 128;
    const int E    = in_sizes[3] / 2;

    k0_prep<<<200, 256>>>(W_dst, W_edge, a_dst, a_edge, ndst);

    const int smem1 = (64 * 128 + 64 * 64) * (int)sizeof(float);  // 48KB
    cudaFuncSetAttribute(k1_gemm, cudaFuncAttributeMaxDynamicSharedMemorySize, smem1);
    k1_gemm<<<(nsrc + 63) / 64, 256, smem1>>>(h_src, W_src, a_src, nsrc);

    k2_node<<<(ndst + 7) / 8, 256>>>(h_dst, ndst);

    // 4 edges per warp, 8 warps per block
    int nwarp3 = (E + 3) / 4;
    k3_edge<<<(nwarp3 + 7) / 8, 256>>>(e_feat, ei, E);

    k4_scan<<<1, 1024>>>(ndst);

    k5_scatter<<<(E + 255) / 256, 256>>>(ei, E);

    k6_agg<<<(ndst + 7) / 8, 256>>>(out, ndst);

    (void)n_in; (void)out_size;
}

// round 8
// speedup vs baseline: 1.6222x; 1.1326x over previous
#include <cuda_runtime.h>
#include <math.h>

#define NSRC 50000
#define NDST 50000
#define EMAX 1600000

// ---------------- scratch (static device globals; no allocs) ----------------
__device__ float g_hs[(size_t)NSRC * 128];     // h_src @ W_src
__device__ float g_esrc[NSRC * 4];             // per-src-node logit component
__device__ float g_edst[NDST * 4];             // per-dst-node logit component
__device__ float g_selog[(size_t)EMAX * 4];    // dst-sorted leaky logits
__device__ int   g_ssrc[EMAX];                 // dst-sorted src indices
__device__ int   g_count[NDST + 1];
__device__ int   g_off[NDST + 1];
__device__ int   g_cur[NDST];
__device__ float g_cdst[128 * 4];              // folded W_dst·a_dst, c[k][h]
__device__ float g_cedge[64 * 4];              // folded W_edge·a_edge

// ---------------- K0: fold W,a -> c vectors; zero histogram ----------------
__global__ void k0_prep(const float* __restrict__ Wdst, const float* __restrict__ Wedge,
                        const float* __restrict__ adst, const float* __restrict__ aedge,
                        int ndst) {
    int t = blockIdx.x * blockDim.x + threadIdx.x;
    int stride = gridDim.x * blockDim.x;
    for (int i = t; i <= ndst; i += stride) g_count[i] = 0;
    if (blockIdx.x == 0) {
        for (int i = threadIdx.x; i < 128 * 4; i += blockDim.x) {
            int k = i >> 2, h = i & 3;
            float s2 = 0.f;
            #pragma unroll
            for (int d = 0; d < 32; d++)
                s2 += Wdst[k * 128 + h * 32 + d] * adst[h * 32 + d];
            g_cdst[i] = s2;
        }
        for (int i = threadIdx.x; i < 64 * 4; i += blockDim.x) {
            int k = i >> 2, h = i & 3;
            float s = 0.f;
            #pragma unroll
            for (int d = 0; d < 32; d++)
                s += Wedge[k * 128 + h * 32 + d] * aedge[h * 32 + d];
            g_cedge[i] = s;
        }
    }
}

// ---------------- KH: dst histogram ----------------
__global__ void kh_hist(const int* __restrict__ ei, int E) {
    int t = blockIdx.x * blockDim.x + threadIdx.x;
    int stride = gridDim.x * blockDim.x;
    for (int e = t; e < E; e += stride)
        atomicAdd(&g_count[ei[E + e]], 1);
}

// ---------------- K4: exclusive scan of histogram (single block) ----------------
__global__ void k4_scan(int n) {
    __shared__ int ssum[1024];
    const int t = threadIdx.x;
    const int chunk = (n + 1023) >> 10;
    const int b = t * chunk;
    int e = b + chunk;
    if (e > n) e = n;
    int s = 0;
    for (int i = b; i < e; i++) s += g_count[i];
    ssum[t] = s;
    __syncthreads();
    for (int off = 1; off < 1024; off <<= 1) {
        int v = (t >= off) ? ssum[t - off] : 0;
        __syncthreads();
        ssum[t] += v;
        __syncthreads();
    }
    int run = (t == 0) ? 0 : ssum[t - 1];
    for (int i = b; i < e; i++) {
        g_off[i] = run;
        g_cur[i] = run;
        run += g_count[i];
    }
    if (t == 1023) g_off[n] = ssum[1023];
}

// ---------------- K1: hs = h_src @ W_src + fused e_src epilogue ----------------
// Block: 256 threads, 64-row x 128-col output tile. Thread: 8 rows x 4 cols.
__global__ void k1_gemm(const float* __restrict__ x, const float* __restrict__ W,
                        const float* __restrict__ asrc, int nrows) {
    extern __shared__ float smem[];
    float* Ws = smem;            // [64][128]  = 32KB
    float* Xs = smem + 64 * 128; // [64][64]   = 16KB
    const int tid = threadIdx.x;
    const int row0 = blockIdx.x * 64;
    const int lane = tid & 31;
    const int c0 = lane * 4;
    const int rbase = (tid >> 5) * 8;

    float4 acc[8];
    #pragma unroll
    for (int r = 0; r < 8; r++) acc[r] = make_float4(0.f, 0.f, 0.f, 0.f);

    for (int kb = 0; kb < 128; kb += 64) {
        for (int i = tid; i < 64 * 128; i += 256) {
            int k = i >> 7, c = i & 127;
            Ws[i] = W[(kb + k) * 128 + c];
        }
        for (int i = tid; i < 64 * 64; i += 256) {
            int r = i >> 6, kk = i & 63;
            int gr = row0 + r;
            Xs[i] = (gr < nrows) ? x[(size_t)gr * 128 + kb + kk] : 0.f;
        }
        __syncthreads();
        #pragma unroll 4
        for (int k = 0; k < 64; k++) {
            float4 w4 = *reinterpret_cast<const float4*>(&Ws[k * 128 + c0]);
            #pragma unroll
            for (int rr = 0; rr < 8; rr++) {
                float xv = Xs[(rbase + rr) * 64 + k];
                acc[rr].x += xv * w4.x;
                acc[rr].y += xv * w4.y;
                acc[rr].z += xv * w4.z;
                acc[rr].w += xv * w4.w;
            }
        }
        __syncthreads();
    }
    #pragma unroll
    for (int rr = 0; rr < 8; rr++) {
        int gr = row0 + rbase + rr;
        if (gr < nrows)
            *reinterpret_cast<float4*>(&g_hs[(size_t)gr * 128 + c0]) = acc[rr];
    }
    // fused e_src: dot output columns with flat a_src ([H,D] contiguous = [128])
    const int h = lane >> 3;
    const float4 a4 = *reinterpret_cast<const float4*>(&asrc[c0]);
    #pragma unroll
    for (int rr = 0; rr < 8; rr++) {
        float p = acc[rr].x * a4.x + acc[rr].y * a4.y + acc[rr].z * a4.z + acc[rr].w * a4.w;
        p += __shfl_xor_sync(0xffffffffu, p, 1);
        p += __shfl_xor_sync(0xffffffffu, p, 2);
        p += __shfl_xor_sync(0xffffffffu, p, 4);
        int gr = row0 + rbase + rr;
        if ((lane & 7) == 0 && gr < nrows)
            g_esrc[gr * 4 + h] = p;
    }
}

// ---------------- K2: dst-node logit components (warp per row) ----------------
__global__ void k2_node(const float* __restrict__ hdst, int ndst) {
    int warp = (blockIdx.x * blockDim.x + threadIdx.x) >> 5;
    int lane = threadIdx.x & 31;
    if (warp >= ndst) return;
    const float* x = hdst + (size_t)warp * 128;
    float4 xv = reinterpret_cast<const float4*>(x)[lane];
    const float4* c4 = reinterpret_cast<const float4*>(g_cdst);
    int k = lane * 4;
    float4 c0v = c4[k], c1v = c4[k + 1], c2v = c4[k + 2], c3v = c4[k + 3];
    float4 a;
    a.x = xv.x * c0v.x + xv.y * c1v.x + xv.z * c2v.x + xv.w * c3v.x;
    a.y = xv.x * c0v.y + xv.y * c1v.y + xv.z * c2v.y + xv.w * c3v.y;
    a.z = xv.x * c0v.z + xv.y * c1v.z + xv.z * c2v.z + xv.w * c3v.z;
    a.w = xv.x * c0v.w + xv.y * c1v.w + xv.z * c2v.w + xv.w * c3v.w;
    #pragma unroll
    for (int off = 16; off; off >>= 1) {
        a.x += __shfl_xor_sync(0xffffffffu, a.x, off);
        a.y += __shfl_xor_sync(0xffffffffu, a.y, off);
        a.z += __shfl_xor_sync(0xffffffffu, a.z, off);
        a.w += __shfl_xor_sync(0xffffffffu, a.w, off);
    }
    if (lane == 0) reinterpret_cast<float4*>(g_edst)[warp] = a;
}

// ---------------- K3: edge logits + leaky relu + DIRECT sorted scatter ----------------
// 8 lanes per edge; c_edge coefficients live in REGISTERS (no LDS in the loop).
// Grid-stride over groups of 4 edges per warp.
__global__ void k3_edge(const float* __restrict__ efeat, const int* __restrict__ ei, int E) {
    const int tid = threadIdx.x;
    const int lane = tid & 31;
    const int g = lane >> 3;            // edge slot within warp (0..3)
    const int sub = lane & 7;           // 8 lanes per edge
    const int warp0 = (blockIdx.x * blockDim.x + tid) >> 5;
    const int nwarps = (gridDim.x * blockDim.x) >> 5;

    // per-lane coefficient registers: heads-major float4 for k = sub*4..+3 and 32+sub*4..+3
    const float4* ce = reinterpret_cast<const float4*>(g_cedge);
    float4 c0a = ce[sub * 4 + 0], c0b = ce[sub * 4 + 1], c0c = ce[sub * 4 + 2], c0d = ce[sub * 4 + 3];
    float4 c1a = ce[32 + sub * 4 + 0], c1b = ce[32 + sub * 4 + 1], c1c = ce[32 + sub * 4 + 2], c1d = ce[32 + sub * 4 + 3];

    const int ngroups = (E + 3) >> 2;
    for (int grp = warp0; grp < ngroups; grp += nwarps) {
        const int e = grp * 4 + g;
        float4 s = make_float4(0.f, 0.f, 0.f, 0.f);
        if (e < E) {
            const float4* x4 = reinterpret_cast<const float4*>(efeat + (size_t)e * 64);
            float4 x0 = x4[sub];
            float4 x1 = x4[8 + sub];
            s.x = x0.x * c0a.x + x0.y * c0b.x + x0.z * c0c.x + x0.w * c0d.x
                + x1.x * c1a.x + x1.y * c1b.x + x1.z * c1c.x + x1.w * c1d.x;
            s.y = x0.x * c0a.y + x0.y * c0b.y + x0.z * c0c.y + x0.w * c0d.y
                + x1.x * c1a.y + x1.y * c1b.y + x1.z * c1c.y + x1.w * c1d.y;
            s.z = x0.x * c0a.z + x0.y * c0b.z + x0.z * c0c.z + x0.w * c0d.z
                + x1.x * c1a.z + x1.y * c1b.z + x1.z * c1c.z + x1.w * c1d.z;
            s.w = x0.x * c0a.w + x0.y * c0b.w + x0.z * c0c.w + x0.w * c0d.w
                + x1.x * c1a.w + x1.y * c1b.w + x1.z * c1c.w + x1.w * c1d.w;
        }
        #pragma unroll
        for (int off = 1; off < 8; off <<= 1) {
            s.x += __shfl_xor_sync(0xffffffffu, s.x, off);
            s.y += __shfl_xor_sync(0xffffffffu, s.y, off);
            s.z += __shfl_xor_sync(0xffffffffu, s.z, off);
            s.w += __shfl_xor_sync(0xffffffffu, s.w, off);
        }
        if (sub == 0 && e < E) {
            int src = ei[e];
            int dst = ei[E + e];
            float4 es = reinterpret_cast<const float4*>(g_esrc)[src];
            float4 ed = reinterpret_cast<const float4*>(g_edst)[dst];
            s.x += es.x + ed.x; s.y += es.y + ed.y; s.z += es.z + ed.z; s.w += es.w + ed.w;
            s.x = s.x > 0.f ? s.x : 0.2f * s.x;
            s.y = s.y > 0.f ? s.y : 0.2f * s.y;
            s.z = s.z > 0.f ? s.z : 0.2f * s.z;
            s.w = s.w > 0.f ? s.w : 0.2f * s.w;
            int pos = atomicAdd(&g_cur[dst], 1);
            g_ssrc[pos] = src;
            reinterpret_cast<float4*>(g_selog)[pos] = s;
        }
    }
}

// ---------------- K6: per-dst softmax + weighted gather-aggregate ----------------
__device__ __forceinline__ void online_upd(float& m, float& s, float v) {
    float nm = fmaxf(m, v);
    s = s * __expf(m - nm) + __expf(v - nm);
    m = nm;
}
__device__ __forceinline__ void warp_merge(float& m, float& s) {
    #pragma unroll
    for (int off = 16; off; off >>= 1) {
        float om = __shfl_xor_sync(0xffffffffu, m, off);
        float os = __shfl_xor_sync(0xffffffffu, s, off);
        float M = fmaxf(m, om);
        s = s * __expf(m - M) + os * __expf(om - M);
        m = M;
    }
}

__global__ void k6_agg(float* __restrict__ out, int ndst) {
    __shared__ float s_alpha[8][32 * 4];   // per-warp: 32 edges x 4 heads
    __shared__ int   s_idx[8][32];
    const int wslot = threadIdx.x >> 5;
    const int warp = (blockIdx.x * blockDim.x + threadIdx.x) >> 5;
    const int lane = threadIdx.x & 31;
    if (warp >= ndst) return;
    const int beg = g_off[warp];
    const int end = g_off[warp + 1];
    float4* orow = reinterpret_cast<float4*>(out + (size_t)warp * 128);
    if (beg == end) {
        orow[lane] = make_float4(0.f, 0.f, 0.f, 0.f);
        return;
    }
    const float4* selog4 = reinterpret_cast<const float4*>(g_selog);
    float m0 = -1e30f, m1 = -1e30f, m2 = -1e30f, m3 = -1e30f;
    float s0 = 0.f, s1 = 0.f, s2 = 0.f, s3 = 0.f;
    for (int i = beg + lane; i < end; i += 32) {
        float4 ev = selog4[i];
        online_upd(m0, s0, ev.x);
        online_upd(m1, s1, ev.y);
        online_upd(m2, s2, ev.z);
        online_upd(m3, s3, ev.w);
    }
    warp_merge(m0, s0);
    warp_merge(m1, s1);
    warp_merge(m2, s2);
    warp_merge(m3, s3);
    const float i0 = 1.f / (s0 + 1e-8f);
    const float i1 = 1.f / (s1 + 1e-8f);
    const float i2 = 1.f / (s2 + 1e-8f);
    const float i3 = 1.f / (s3 + 1e-8f);
    const int myh = lane >> 3;

    const float4* hs4 = reinterpret_cast<const float4*>(g_hs);
    float4 acc = make_float4(0.f, 0.f, 0.f, 0.f);
    for (int base = beg; base < end; base += 32) {
        int myi = base + lane;
        if (myi < end) {
            float4 ev = selog4[myi];
            float4 af;
            af.x = __expf(ev.x - m0) * i0;
            af.y = __expf(ev.y - m1) * i1;
            af.z = __expf(ev.z - m2) * i2;
            af.w = __expf(ev.w - m3) * i3;
            reinterpret_cast<float4*>(&s_alpha[wslot][0])[lane] = af;
            s_idx[wslot][lane] = g_ssrc[myi];
        }
        __syncwarp();
        int n = end - base;
        if (n > 32) n = 32;
        const float* ap = &s_alpha[wslot][myh];
        #pragma unroll 4
        for (int j = 0; j < n; j++) {
            float al = ap[j * 4];
            int src = s_idx[wslot][j];
            float4 xv = hs4[(size_t)src * 32 + lane];
            acc.x += al * xv.x;
            acc.y += al * xv.y;
            acc.z += al * xv.z;
            acc.w += al * xv.w;
        }
        __syncwarp();
    }
    orow[lane] = acc;
}

// ---------------- launch ----------------
extern "C" void kernel_launch(void* const* d_in, const int* in_sizes, int n_in,
                              void* d_out, int out_size) {
    const float* h_src   = (const float*)d_in[0];
    const float* h_dst   = (const float*)d_in[1];
    const float* e_feat  = (const float*)d_in[2];
    const int*   ei      = (const int*)d_in[3];
    const float* W_src   = (const float*)d_in[4];
    const float* W_dst   = (const float*)d_in[5];
    const float* W_edge  = (const float*)d_in[6];
    const float* a_src   = (const float*)d_in[7];
    const float* a_dst   = (const float*)d_in[8];
    const float* a_edge  = (const float*)d_in[9];
    float* out = (float*)d_out;

    const int nsrc = in_sizes[0] / 128;
    const int ndst = in_sizes[1] / 128;
    const int E    = in_sizes[3] / 2;

    k0_prep<<<200, 256>>>(W_dst, W_edge, a_dst, a_edge, ndst);
    kh_hist<<<592, 256>>>(ei, E);
    k4_scan<<<1, 1024>>>(ndst);

    const int smem1 = (64 * 128 + 64 * 64) * (int)sizeof(float);  // 48KB
    cudaFuncSetAttribute(k1_gemm, cudaFuncAttributeMaxDynamicSharedMemorySize, smem1);
    k1_gemm<<<(nsrc + 63) / 64, 256, smem1>>>(h_src, W_src, a_src, nsrc);

    k2_node<<<(ndst + 7) / 8, 256>>>(h_dst, ndst);

    // k3: fixed grid, grid-stride over edge groups (4 edges per warp)
    k3_edge<<<1184, 256>>>(e_feat, ei, E);

    k6_agg<<<(ndst + 7) / 8, 256>>>(out, ndst);

    (void)n_in; (void)out_size;
}

// round 9
// speedup vs baseline: 1.7469x; 1.0769x over previous
#include <cuda_runtime.h>
#include <math.h>

#define NSRC 50000
#define NDST 50000
#define EMAX 1600000

// ---------------- scratch (static device globals; no allocs) ----------------
__device__ float g_hs[(size_t)NSRC * 128];     // h_src @ W_src
__device__ float g_esrc[NSRC * 4];             // per-src-node logit component
__device__ float g_edst[NDST * 4];             // per-dst-node logit component
__device__ float g_erec[(size_t)EMAX * 8];     // dst-sorted 32B records {logit4, src, pad}
__device__ int   g_count[NDST + 1];
__device__ int   g_off[NDST + 1];
__device__ int   g_cur[NDST];
__device__ float g_cdst[128 * 4];              // folded W_dst·a_dst, c[k][h]
__device__ float g_cedge[64 * 4];              // folded W_edge·a_edge

// ---------------- K0: fold W,a -> c vectors; zero histogram ----------------
__global__ void k0_prep(const float* __restrict__ Wdst, const float* __restrict__ Wedge,
                        const float* __restrict__ adst, const float* __restrict__ aedge,
                        int ndst) {
    int t = blockIdx.x * blockDim.x + threadIdx.x;
    int stride = gridDim.x * blockDim.x;
    for (int i = t; i <= ndst; i += stride) g_count[i] = 0;
    if (blockIdx.x == 0) {
        for (int i = threadIdx.x; i < 128 * 4; i += blockDim.x) {
            int k = i >> 2, h = i & 3;
            float s2 = 0.f;
            #pragma unroll
            for (int d = 0; d < 32; d++)
                s2 += Wdst[k * 128 + h * 32 + d] * adst[h * 32 + d];
            g_cdst[i] = s2;
        }
        for (int i = threadIdx.x; i < 64 * 4; i += blockDim.x) {
            int k = i >> 2, h = i & 3;
            float s = 0.f;
            #pragma unroll
            for (int d = 0; d < 32; d++)
                s += Wedge[k * 128 + h * 32 + d] * aedge[h * 32 + d];
            g_cedge[i] = s;
        }
    }
}

// ---------------- KH: dst histogram ----------------
__global__ void kh_hist(const int* __restrict__ ei, int E) {
    int t = blockIdx.x * blockDim.x + threadIdx.x;
    int stride = gridDim.x * blockDim.x;
    for (int e = t; e < E; e += stride)
        atomicAdd(&g_count[ei[E + e]], 1);
}

// ---------------- K4: exclusive scan of histogram (single block) ----------------
__global__ void k4_scan(int n) {
    __shared__ int ssum[1024];
    const int t = threadIdx.x;
    const int chunk = (n + 1023) >> 10;
    const int b = t * chunk;
    int e = b + chunk;
    if (e > n) e = n;
    int s = 0;
    for (int i = b; i < e; i++) s += g_count[i];
    ssum[t] = s;
    __syncthreads();
    for (int off = 1; off < 1024; off <<= 1) {
        int v = (t >= off) ? ssum[t - off] : 0;
        __syncthreads();
        ssum[t] += v;
        __syncthreads();
    }
    int run = (t == 0) ? 0 : ssum[t - 1];
    for (int i = b; i < e; i++) {
        g_off[i] = run;
        g_cur[i] = run;
        run += g_count[i];
    }
    if (t == 1023) g_off[n] = ssum[1023];
}

// ---------------- K1: hs = h_src @ W_src + fused e_src epilogue ----------------
// Block: 256 threads, 64-row x 128-col output tile. Thread: 8 rows x 4 cols.
// __launch_bounds__(256,4): cap regs at 64 so 4 blocks/SM (occ 50%, was 25%).
__global__ void __launch_bounds__(256, 4)
k1_gemm(const float* __restrict__ x, const float* __restrict__ W,
        const float* __restrict__ asrc, int nrows) {
    extern __shared__ float smem[];
    float* Ws = smem;            // [64][128]  = 32KB
    float* Xs = smem + 64 * 128; // [64][64]   = 16KB
    const int tid = threadIdx.x;
    const int row0 = blockIdx.x * 64;
    const int lane = tid & 31;
    const int c0 = lane * 4;
    const int rbase = (tid >> 5) * 8;

    float4 acc[8];
    #pragma unroll
    for (int r = 0; r < 8; r++) acc[r] = make_float4(0.f, 0.f, 0.f, 0.f);

    for (int kb = 0; kb < 128; kb += 64) {
        for (int i = tid; i < 64 * 128; i += 256) {
            int k = i >> 7, c = i & 127;
            Ws[i] = W[(kb + k) * 128 + c];
        }
        for (int i = tid; i < 64 * 64; i += 256) {
            int r = i >> 6, kk = i & 63;
            int gr = row0 + r;
            Xs[i] = (gr < nrows) ? x[(size_t)gr * 128 + kb + kk] : 0.f;
        }
        __syncthreads();
        #pragma unroll 4
        for (int k = 0; k < 64; k++) {
            float4 w4 = *reinterpret_cast<const float4*>(&Ws[k * 128 + c0]);
            #pragma unroll
            for (int rr = 0; rr < 8; rr++) {
                float xv = Xs[(rbase + rr) * 64 + k];
                acc[rr].x += xv * w4.x;
                acc[rr].y += xv * w4.y;
                acc[rr].z += xv * w4.z;
                acc[rr].w += xv * w4.w;
            }
        }
        __syncthreads();
    }
    #pragma unroll
    for (int rr = 0; rr < 8; rr++) {
        int gr = row0 + rbase + rr;
        if (gr < nrows)
            *reinterpret_cast<float4*>(&g_hs[(size_t)gr * 128 + c0]) = acc[rr];
    }
    // fused e_src: dot output columns with flat a_src ([H,D] contiguous = [128])
    const int h = lane >> 3;
    const float4 a4 = *reinterpret_cast<const float4*>(&asrc[c0]);
    #pragma unroll
    for (int rr = 0; rr < 8; rr++) {
        float p = acc[rr].x * a4.x + acc[rr].y * a4.y + acc[rr].z * a4.z + acc[rr].w * a4.w;
        p += __shfl_xor_sync(0xffffffffu, p, 1);
        p += __shfl_xor_sync(0xffffffffu, p, 2);
        p += __shfl_xor_sync(0xffffffffu, p, 4);
        int gr = row0 + rbase + rr;
        if ((lane & 7) == 0 && gr < nrows)
            g_esrc[gr * 4 + h] = p;
    }
}

// ---------------- K2: dst-node logit components (warp per row) ----------------
__global__ void k2_node(const float* __restrict__ hdst, int ndst) {
    int warp = (blockIdx.x * blockDim.x + threadIdx.x) >> 5;
    int lane = threadIdx.x & 31;
    if (warp >= ndst) return;
    const float* x = hdst + (size_t)warp * 128;
    float4 xv = reinterpret_cast<const float4*>(x)[lane];
    const float4* c4 = reinterpret_cast<const float4*>(g_cdst);
    int k = lane * 4;
    float4 c0v = c4[k], c1v = c4[k + 1], c2v = c4[k + 2], c3v = c4[k + 3];
    float4 a;
    a.x = xv.x * c0v.x + xv.y * c1v.x + xv.z * c2v.x + xv.w * c3v.x;
    a.y = xv.x * c0v.y + xv.y * c1v.y + xv.z * c2v.y + xv.w * c3v.y;
    a.z = xv.x * c0v.z + xv.y * c1v.z + xv.z * c2v.z + xv.w * c3v.z;
    a.w = xv.x * c0v.w + xv.y * c1v.w + xv.z * c2v.w + xv.w * c3v.w;
    #pragma unroll
    for (int off = 16; off; off >>= 1) {
        a.x += __shfl_xor_sync(0xffffffffu, a.x, off);
        a.y += __shfl_xor_sync(0xffffffffu, a.y, off);
        a.z += __shfl_xor_sync(0xffffffffu, a.z, off);
        a.w += __shfl_xor_sync(0xffffffffu, a.w, off);
    }
    if (lane == 0) reinterpret_cast<float4*>(g_edst)[warp] = a;
}

// ---------------- K3: edge logits + leaky relu + DIRECT sorted scatter ----------------
// 8 lanes per edge; c_edge coefficients in registers. 32B sector-aligned record store.
__global__ void k3_edge(const float* __restrict__ efeat, const int* __restrict__ ei, int E) {
    const int tid = threadIdx.x;
    const int lane = tid & 31;
    const int g = lane >> 3;            // edge slot within warp (0..3)
    const int sub = lane & 7;           // 8 lanes per edge
    const int warp0 = (blockIdx.x * blockDim.x + tid) >> 5;
    const int nwarps = (gridDim.x * blockDim.x) >> 5;

    const float4* ce = reinterpret_cast<const float4*>(g_cedge);
    float4 c0a = ce[sub * 4 + 0], c0b = ce[sub * 4 + 1], c0c = ce[sub * 4 + 2], c0d = ce[sub * 4 + 3];
    float4 c1a = ce[32 + sub * 4 + 0], c1b = ce[32 + sub * 4 + 1], c1c = ce[32 + sub * 4 + 2], c1d = ce[32 + sub * 4 + 3];

    const int ngroups = (E + 3) >> 2;
    for (int grp = warp0; grp < ngroups; grp += nwarps) {
        const int e = grp * 4 + g;
        float4 s = make_float4(0.f, 0.f, 0.f, 0.f);
        if (e < E) {
            const float4* x4 = reinterpret_cast<const float4*>(efeat + (size_t)e * 64);
            float4 x0 = x4[sub];
            float4 x1 = x4[8 + sub];
            s.x = x0.x * c0a.x + x0.y * c0b.x + x0.z * c0c.x + x0.w * c0d.x
                + x1.x * c1a.x + x1.y * c1b.x + x1.z * c1c.x + x1.w * c1d.x;
            s.y = x0.x * c0a.y + x0.y * c0b.y + x0.z * c0c.y + x0.w * c0d.y
                + x1.x * c1a.y + x1.y * c1b.y + x1.z * c1c.y + x1.w * c1d.y;
            s.z = x0.x * c0a.z + x0.y * c0b.z + x0.z * c0c.z + x0.w * c0d.z
                + x1.x * c1a.z + x1.y * c1b.z + x1.z * c1c.z + x1.w * c1d.z;
            s.w = x0.x * c0a.w + x0.y * c0b.w + x0.z * c0c.w + x0.w * c0d.w
                + x1.x * c1a.w + x1.y * c1b.w + x1.z * c1c.w + x1.w * c1d.w;
        }
        #pragma unroll
        for (int off = 1; off < 8; off <<= 1) {
            s.x += __shfl_xor_sync(0xffffffffu, s.x, off);
            s.y += __shfl_xor_sync(0xffffffffu, s.y, off);
            s.z += __shfl_xor_sync(0xffffffffu, s.z, off);
            s.w += __shfl_xor_sync(0xffffffffu, s.w, off);
        }
        if (sub == 0 && e < E) {
            int src = ei[e];
            int dst = ei[E + e];
            float4 es = reinterpret_cast<const float4*>(g_esrc)[src];
            float4 ed = reinterpret_cast<const float4*>(g_edst)[dst];
            s.x += es.x + ed.x; s.y += es.y + ed.y; s.z += es.z + ed.z; s.w += es.w + ed.w;
            s.x = s.x > 0.f ? s.x : 0.2f * s.x;
            s.y = s.y > 0.f ? s.y : 0.2f * s.y;
            s.z = s.z > 0.f ? s.z : 0.2f * s.z;
            s.w = s.w > 0.f ? s.w : 0.2f * s.w;
            int pos = atomicAdd(&g_cur[dst], 1);
            float4* rec = reinterpret_cast<float4*>(&g_erec[(size_t)pos * 8]);
            rec[0] = s;
            rec[1] = make_float4(__int_as_float(src), 0.f, 0.f, 0.f);
        }
    }
}

// ---------------- K6: per-dst softmax + weighted gather-aggregate ----------------
__device__ __forceinline__ void online_upd(float& m, float& s, float v) {
    float nm = fmaxf(m, v);
    s = s * __expf(m - nm) + __expf(v - nm);
    m = nm;
}
__device__ __forceinline__ void warp_merge(float& m, float& s) {
    #pragma unroll
    for (int off = 16; off; off >>= 1) {
        float om = __shfl_xor_sync(0xffffffffu, m, off);
        float os = __shfl_xor_sync(0xffffffffu, s, off);
        float M = fmaxf(m, om);
        s = s * __expf(m - M) + os * __expf(om - M);
        m = M;
    }
}

__global__ void k6_agg(float* __restrict__ out, int ndst) {
    __shared__ float s_alpha[8][32 * 4];   // per-warp: 32 edges x 4 heads
    __shared__ int   s_idx[8][32];
    const int wslot = threadIdx.x >> 5;
    const int warp = (blockIdx.x * blockDim.x + threadIdx.x) >> 5;
    const int lane = threadIdx.x & 31;
    if (warp >= ndst) return;
    const int beg = g_off[warp];
    const int end = g_off[warp + 1];
    float4* orow = reinterpret_cast<float4*>(out + (size_t)warp * 128);
    if (beg == end) {
        orow[lane] = make_float4(0.f, 0.f, 0.f, 0.f);
        return;
    }
    float m0 = -1e30f, m1 = -1e30f, m2 = -1e30f, m3 = -1e30f;
    float s0 = 0.f, s1 = 0.f, s2 = 0.f, s3 = 0.f;
    for (int i = beg + lane; i < end; i += 32) {
        float4 ev = *reinterpret_cast<const float4*>(&g_erec[(size_t)i * 8]);
        online_upd(m0, s0, ev.x);
        online_upd(m1, s1, ev.y);
        online_upd(m2, s2, ev.z);
        online_upd(m3, s3, ev.w);
    }
    warp_merge(m0, s0);
    warp_merge(m1, s1);
    warp_merge(m2, s2);
    warp_merge(m3, s3);
    const float i0 = 1.f / (s0 + 1e-8f);
    const float i1 = 1.f / (s1 + 1e-8f);
    const float i2 = 1.f / (s2 + 1e-8f);
    const float i3 = 1.f / (s3 + 1e-8f);
    const int myh = lane >> 3;

    const float4* hs4 = reinterpret_cast<const float4*>(g_hs);
    float4 acc = make_float4(0.f, 0.f, 0.f, 0.f);
    for (int base = beg; base < end; base += 32) {
        int myi = base + lane;
        if (myi < end) {
            float4 ev = *reinterpret_cast<const float4*>(&g_erec[(size_t)myi * 8]);
            int srci = __float_as_int(g_erec[(size_t)myi * 8 + 4]);
            float4 af;
            af.x = __expf(ev.x - m0) * i0;
            af.y = __expf(ev.y - m1) * i1;
            af.z = __expf(ev.z - m2) * i2;
            af.w = __expf(ev.w - m3) * i3;
            reinterpret_cast<float4*>(&s_alpha[wslot][0])[lane] = af;
            s_idx[wslot][lane] = srci;
        }
        __syncwarp();
        int n = end - base;
        if (n > 32) n = 32;
        const float* ap = &s_alpha[wslot][myh];
        #pragma unroll 4
        for (int j = 0; j < n; j++) {
            float al = ap[j * 4];
            int src = s_idx[wslot][j];
            float4 xv = hs4[(size_t)src * 32 + lane];
            acc.x += al * xv.x;
            acc.y += al * xv.y;
            acc.z += al * xv.z;
            acc.w += al * xv.w;
        }
        __syncwarp();
    }
    orow[lane] = acc;
}

// ---------------- launch ----------------
extern "C" void kernel_launch(void* const* d_in, const int* in_sizes, int n_in,
                              void* d_out, int out_size) {
    const float* h_src   = (const float*)d_in[0];
    const float* h_dst   = (const float*)d_in[1];
    const float* e_feat  = (const float*)d_in[2];
    const int*   ei      = (const int*)d_in[3];
    const float* W_src   = (const float*)d_in[4];
    const float* W_dst   = (const float*)d_in[5];
    const float* W_edge  = (const float*)d_in[6];
    const float* a_src   = (const float*)d_in[7];
    const float* a_dst   = (const float*)d_in[8];
    const float* a_edge  = (const float*)d_in[9];
    float* out = (float*)d_out;

    const int nsrc = in_sizes[0] / 128;
    const int ndst = in_sizes[1] / 128;
    const int E    = in_sizes[3] / 2;

    k0_prep<<<200, 256>>>(W_dst, W_edge, a_dst, a_edge, ndst);
    kh_hist<<<592, 256>>>(ei, E);
    k4_scan<<<1, 1024>>>(ndst);

    const int smem1 = (64 * 128 + 64 * 64) * (int)sizeof(float);  // 48KB
    cudaFuncSetAttribute(k1_gemm, cudaFuncAttributeMaxDynamicSharedMemorySize, smem1);
    k1_gemm<<<(nsrc + 63) / 64, 256, smem1>>>(h_src, W_src, a_src, nsrc);

    k2_node<<<(ndst + 7) / 8, 256>>>(h_dst, ndst);

    k3_edge<<<1184, 256>>>(e_feat, ei, E);

    k6_agg<<<(ndst + 7) / 8, 256>>>(out, ndst);

    (void)n_in; (void)out_size;
}